// round 13
// baseline (speedup 1.0000x reference)
#include <cuda_runtime.h>
#include <cuda_fp16.h>
#include <mma.h>
#include <math.h>
#include <stdint.h>

using namespace nvcuda;

// Problem constants
#define BB 8
#define TT 2048
#define DD 1024
#define EE 8
#define FF 4096
#define KK 2
#define NT (BB*TT)          // 16384 tokens
#define NROWS (NT*KK)       // 32768 token-expert assignments

// GEMM tiling: 64x128 CTA tile, 32x32 warp tile -> 3 CTAs/SM (24 warps)
#define BM 64
#define BN 128
#define BKT 64              // 64 halves = 128B per row per K tile
#define BKP 72              // padded K stride in halves
#define CN 132              // padded fp32 staging stride for epilogue
#define TILE_BYTES ((BM+BN)*BKP*2)     // 27648 B per stage
#define NSTAGE 2
#define SMEM_BYTES (NSTAGE*TILE_BYTES) // 55296 B -> 3 CTAs/SM (166KB), regs capped at 85

// ---------------- device scratch (NEVER passed as kernel args from host) ----------------
__device__ int    g_cnt[EE];            // zero at load; reset by combine_k each run
__device__ int    g_off[EE+1];
__device__ int    g_list[NROWS];
__device__ int    g_slot[NROWS];
__device__ unsigned char g_tope[NROWS];
__device__ float  g_topv[NROWS];
__device__ float  g_denom[BB*KK];
__device__ __half g_h[(size_t)NROWS*FF];    // 256 MB
__device__ float  g_y[(size_t)NROWS*DD];    // 128 MB
__device__ __half g_tokh[(size_t)NT*DD];    //  32 MB
__device__ __half g_w1h[(size_t)EE*FF*DD];  //  64 MB
__device__ __half g_w2h[(size_t)EE*DD*FF];  //  64 MB

// ---------------- helpers ----------------
__device__ __forceinline__ uint32_t s2u(const void* p) {
    uint32_t a;
    asm("{ .reg .u64 t; cvta.to.shared.u64 t, %1; cvt.u32.u64 %0, t; }" : "=r"(a) : "l"(p));
    return a;
}
__device__ __forceinline__ void cp16(uint32_t s, const void* g) {
    asm volatile("cp.async.cg.shared.global [%0], [%1], 16;" :: "r"(s), "l"(g));
}
__device__ __forceinline__ void cp_commit() {
    asm volatile("cp.async.commit_group;" ::: "memory");
}
template<int N>
__device__ __forceinline__ void cp_wait() {
    asm volatile("cp.async.wait_group %0;" :: "n"(N) : "memory");
}

// ---------------- prep: ALL fp32 -> fp16 conversions in one launch ----------------
__global__ void f2h_all_k(const float* __restrict__ tokens,
                          const float* __restrict__ w1,
                          const float* __restrict__ w2) {
    const long long n_tok = (long long)NT * DD / 4;
    const long long n_w1  = (long long)EE * FF * DD / 4;
    const long long n_w2  = (long long)EE * DD * FF / 4;
    long long i = (long long)blockIdx.x * blockDim.x + threadIdx.x;
    if (i >= n_tok + n_w1 + n_w2) return;
    const float* in; __half* out; long long j;
    if (i < n_tok)            { in = tokens; out = g_tokh; j = i; }
    else if (i < n_tok + n_w1){ in = w1;     out = g_w1h;  j = i - n_tok; }
    else                      { in = w2;     out = g_w2h;  j = i - n_tok - n_w1; }
    float4 v = reinterpret_cast<const float4*>(in)[j];
    __half2 h01 = __floats2half2_rn(v.x, v.y);
    __half2 h23 = __floats2half2_rn(v.z, v.w);
    uint2 pk;
    pk.x = *reinterpret_cast<uint32_t*>(&h01);
    pk.y = *reinterpret_cast<uint32_t*>(&h23);
    reinterpret_cast<uint2*>(out)[j] = pk;
}

// ---------------- routing ----------------
__global__ void gate_topk_k(const float* __restrict__ tokens,
                            const float* __restrict__ gw,
                            const float* __restrict__ gb) {
    int warp = threadIdx.x >> 5, lane = threadIdx.x & 31;
    int t = blockIdx.x * 8 + warp;
    const float* x = tokens + (size_t)t * DD;
    float xr[32];
#pragma unroll
    for (int c = 0; c < 32; c++) xr[c] = x[c * 32 + lane];
    float best0 = -1e30f, best1 = -1e30f;
    int e0 = 0, e1 = 0;
#pragma unroll
    for (int e = 0; e < EE; e++) {
        const float* w = gw + e * DD;
        float acc = 0.f;
#pragma unroll
        for (int c = 0; c < 32; c++) acc += xr[c] * w[c * 32 + lane];
#pragma unroll
        for (int o = 16; o > 0; o >>= 1) acc += __shfl_xor_sync(0xffffffffu, acc, o);
        acc += gb[e];
        if (acc > best0) { best1 = best0; e1 = e0; best0 = acc; e0 = e; }
        else if (acc > best1) { best1 = acc; e1 = e; }
    }
    if (lane == 0) {
        g_tope[t * 2] = (unsigned char)e0;
        g_tope[t * 2 + 1] = (unsigned char)e1;
        g_topv[t * 2] = best0;
        g_topv[t * 2 + 1] = best1;
        atomicAdd(&g_cnt[e0], 1);
        atomicAdd(&g_cnt[e1], 1);
    }
}

// single block: exclusive scan of g_cnt then compact fill (smem counters)
__global__ void scan_fill_k() {
    __shared__ int sfill[EE];
    int tid = threadIdx.x;
    if (tid == 0) {
        int o = 0;
        for (int e = 0; e < EE; e++) { g_off[e] = o; o += g_cnt[e]; }
        g_off[EE] = o;
    }
    if (tid < EE) sfill[tid] = 0;
    __syncthreads();
    for (int idx = tid; idx < NROWS; idx += blockDim.x) {
        int e = g_tope[idx];
        int pos = g_off[e] + atomicAdd(&sfill[e], 1);
        g_list[pos] = idx >> 1;
        g_slot[idx] = pos;
    }
}

__global__ void denom_k() {
    int b = blockIdx.x >> 1, k = blockIdx.x & 1;
    __shared__ float s[256];
    float a = 0.f;
    for (int i = 0; i < TT; i += 256) {
        int t = i + threadIdx.x;
        a += expf(g_topv[(size_t)(b * TT + t) * 2 + k]);
    }
    s[threadIdx.x] = a;
    __syncthreads();
    for (int o = 128; o > 0; o >>= 1) {
        if (threadIdx.x < o) s[threadIdx.x] += s[threadIdx.x + o];
        __syncthreads();
    }
    if (threadIdx.x == 0) g_denom[blockIdx.x] = s[0];
}

// ---------------- grouped GEMM: 64x128 tile, 32x32 warp tile, 2-stage cp.async ----------------
template<bool GATHER>
__global__ void __launch_bounds__(256, 3) ffn_gemm(const float* __restrict__ bias,
                                                   int Kdim, int Ntot) {
    int e = blockIdx.z;
    int cnt_e = g_cnt[e];
    int mbase = blockIdx.y * BM;
    if (mbase >= cnt_e) return;
    int rowbase = g_off[e] + mbase;
    int nbase = blockIdx.x * BN;

    extern __shared__ __half smem[];
    uint32_t smem_u = s2u(smem);
    __shared__ const __half* arow[BM];

    int tid = threadIdx.x;
    if (tid < BM) {
        int r = (mbase + tid < cnt_e) ? tid : 0;   // clamp invalid rows
        int gr = rowbase + r;
        arow[tid] = GATHER ? (g_tokh + (size_t)g_list[gr] * Kdim)
                           : (g_h + (size_t)gr * Kdim);
    }
    __syncthreads();

    const __half* Bsrc = GATHER ? g_w1h : g_w2h;
    const __half* Bb = Bsrc + (size_t)e * Ntot * Kdim + (size_t)nbase * Kdim;

    wmma::fragment<wmma::accumulator, 16, 16, 16, float> acc[2][2];
#pragma unroll
    for (int i = 0; i < 2; i++)
#pragma unroll
        for (int j = 0; j < 2; j++) wmma::fill_fragment(acc[i][j], 0.f);

    int wid = tid >> 5;
    int wm = wid & 1;   // 2 warp-rows -> 32 rows each
    int wn = wid >> 1;  // 4 warp-cols -> 32 cols each

    int ktiles = Kdim / BKT;

    auto issue = [&](int s, int k0) {
        uint32_t baseA = smem_u + (uint32_t)s * TILE_BYTES;
        uint32_t baseB = baseA + (uint32_t)BM * BKP * 2;
        // A: 64 rows x 8 chunks = 512
#pragma unroll
        for (int i = 0; i < 2; i++) {
            int f = tid + i * 256;
            int r = f >> 3, c = (f & 7) * 8;
            cp16(baseA + (uint32_t)(r * BKP + c) * 2, arow[r] + k0 + c);
        }
        // B: 128 rows x 8 chunks = 1024
#pragma unroll
        for (int i = 0; i < 4; i++) {
            int f = tid + i * 256;
            int r = f >> 3, c = (f & 7) * 8;
            cp16(baseB + (uint32_t)(r * BKP + c) * 2, Bb + (size_t)r * Kdim + k0 + c);
        }
        cp_commit();
    };

    issue(0, 0);

    for (int kt = 0; kt < ktiles; kt++) {
        if (kt + 1 < ktiles) issue((kt + 1) & 1, (kt + 1) * BKT);
        else                 cp_commit();   // keep group count aligned
        cp_wait<1>();
        __syncthreads();

        const __half* As = smem + (size_t)(kt & 1) * ((BM + BN) * BKP);
        const __half* Bs = As + BM * BKP;

#pragma unroll
        for (int kk = 0; kk < BKT; kk += 16) {
            wmma::fragment<wmma::matrix_a, 16, 16, 16, __half, wmma::row_major> af[2];
#pragma unroll
            for (int i = 0; i < 2; i++)
                wmma::load_matrix_sync(af[i], &As[(wm * 32 + i * 16) * BKP + kk], BKP);
#pragma unroll
            for (int j = 0; j < 2; j++) {
                wmma::fragment<wmma::matrix_b, 16, 16, 16, __half, wmma::col_major> bf;
                wmma::load_matrix_sync(bf, &Bs[(wn * 32 + j * 16) * BKP + kk], BKP);
#pragma unroll
                for (int i = 0; i < 2; i++)
                    wmma::mma_sync(acc[i][j], af[i], bf, acc[i][j]);
            }
        }
        __syncthreads();   // all warps done with this stage before overwrite
    }

    // ---------------- single-pass epilogue: 64 x CN fp32 staging, one sync ----------------
    float* Cs = reinterpret_cast<float*>(smem);   // 64 x 132 x 4 = 33792 B <= SMEM_BYTES
#pragma unroll
    for (int i = 0; i < 2; i++)
#pragma unroll
        for (int j = 0; j < 2; j++)
            wmma::store_matrix_sync(&Cs[(wm * 32 + i * 16) * CN + wn * 32 + j * 16],
                                    acc[i][j], CN, wmma::mem_row_major);
    __syncthreads();

    // write sweep: 64 rows x 32 float4 = 2048 items
#pragma unroll
    for (int it = 0; it < 8; it++) {
        int f = tid + it * 256;
        int r = f >> 5, c = (f & 31) * 4;
        if (mbase + r < cnt_e) {
            float4 v = *reinterpret_cast<float4*>(&Cs[r * CN + c]);
            int col = nbase + c;
            float4 bb = *reinterpret_cast<const float4*>(bias + (size_t)e * Ntot + col);
            v.x += bb.x; v.y += bb.y; v.z += bb.z; v.w += bb.w;
            if (GATHER) {
                v.x = fmaxf(v.x, 0.f); v.y = fmaxf(v.y, 0.f);
                v.z = fmaxf(v.z, 0.f); v.w = fmaxf(v.w, 0.f);
                __half2 h01 = __floats2half2_rn(v.x, v.y);
                __half2 h23 = __floats2half2_rn(v.z, v.w);
                uint2 pk;
                pk.x = *reinterpret_cast<uint32_t*>(&h01);
                pk.y = *reinterpret_cast<uint32_t*>(&h23);
                *reinterpret_cast<uint2*>(&g_h[(size_t)(rowbase + r) * Ntot + col]) = pk;
            } else {
                *reinterpret_cast<float4*>(&g_y[(size_t)(rowbase + r) * Ntot + col]) = v;
            }
        }
    }
}

// out[t] = g0*y[slot0] + g1*y[slot1]; block 0 also resets g_cnt for next run
__global__ void combine_k(float* __restrict__ out) {
    int t = blockIdx.x;
    if (t == 0 && threadIdx.x < EE) g_cnt[threadIdx.x] = 0;
    int b = t / TT;
    float g0 = expf(g_topv[2 * t])     / g_denom[b * 2 + 0];
    float g1 = expf(g_topv[2 * t + 1]) / g_denom[b * 2 + 1];
    const float4* y0 = reinterpret_cast<const float4*>(g_y + (size_t)g_slot[2 * t] * DD);
    const float4* y1 = reinterpret_cast<const float4*>(g_y + (size_t)g_slot[2 * t + 1] * DD);
    float4 a = y0[threadIdx.x];
    float4 c = y1[threadIdx.x];
    float4 r;
    r.x = g0 * a.x + g1 * c.x;
    r.y = g0 * a.y + g1 * c.y;
    r.z = g0 * a.z + g1 * c.z;
    r.w = g0 * a.w + g1 * c.w;
    reinterpret_cast<float4*>(out + (size_t)t * DD)[threadIdx.x] = r;
}

// ---------------- launch: GEMM1 is launch index 3 (the profiled slot) ----------------
extern "C" void kernel_launch(void* const* d_in, const int* in_sizes, int n_in,
                              void* d_out, int out_size) {
    const float* tokens = (const float*)d_in[0];
    const float* gate_w = (const float*)d_in[1];
    const float* gate_b = (const float*)d_in[2];
    const float* w1     = (const float*)d_in[3];
    const float* b1     = (const float*)d_in[4];
    const float* w2     = (const float*)d_in[5];
    const float* b2     = (const float*)d_in[6];
    float* out = (float*)d_out;

    cudaFuncSetAttribute(ffn_gemm<true>,
                         cudaFuncAttributeMaxDynamicSharedMemorySize, SMEM_BYTES);
    cudaFuncSetAttribute(ffn_gemm<false>,
                         cudaFuncAttributeMaxDynamicSharedMemorySize, SMEM_BYTES);

    long long n4_total = (long long)NT * DD / 4 + (long long)EE * FF * DD / 2;
    f2h_all_k<<<(unsigned)((n4_total + 255) / 256), 256>>>(tokens, w1, w2);   // 0
    gate_topk_k<<<NT / 8, 256>>>(tokens, gate_w, gate_b);                      // 1
    scan_fill_k<<<1, 1024>>>();                                                // 2
    ffn_gemm<true><<<dim3(FF / BN, NROWS / BM, EE), 256, SMEM_BYTES>>>(b1, DD, FF);   // 3 <- ncu
    ffn_gemm<false><<<dim3(DD / BN, NROWS / BM, EE), 256, SMEM_BYTES>>>(b2, FF, DD);  // 4
    denom_k<<<BB * KK, 256>>>();                                               // 5
    combine_k<<<NT, 256>>>(out);                                               // 6
}

// round 14
// speedup vs baseline: 1.1367x; 1.1367x over previous
#include <cuda_runtime.h>
#include <cuda_fp16.h>
#include <mma.h>
#include <math.h>
#include <stdint.h>

using namespace nvcuda;

// Problem constants
#define BB 8
#define TT 2048
#define DD 1024
#define EE 8
#define FF 4096
#define KK 2
#define NT (BB*TT)          // 16384 tokens
#define NROWS (NT*KK)       // 32768 token-expert assignments

// GEMM tiling (champion config: 128x128 CTA tile, 64x64-ish warp tiles)
#define BM 128
#define BN 128
#define BKT 64              // 64 halves = 128B per row per tile
#define BKP 72              // padded K stride in halves
#define CN 132              // padded fp32 staging stride for single-pass epilogue
#define TILE_BYTES (2*BM*BKP*2)        // A+B one stage = 36864 B
#define NSTAGE 3
#define SMEM_BYTES (NSTAGE*TILE_BYTES) // 110592 B -> 2 CTAs/SM
#define MAXWRK (NROWS/BM + EE)         // 264 worst-case work items

// ---------------- device scratch (NEVER passed as kernel args from host) ----------------
__device__ int    g_cnt[EE];            // zero at load; reset by combine_k each run
__device__ int    g_off[EE+1];
__device__ int    g_nwrk;
__device__ int    g_wrk[MAXWRK];        // (e << 20) | m-block
__device__ int    g_list[NROWS];
__device__ int    g_slot[NROWS];
__device__ unsigned char g_tope[NROWS];
__device__ float  g_topv[NROWS];
__device__ float  g_denom[BB*KK];
__device__ __half g_h[(size_t)NROWS*FF];    // 256 MB
__device__ float  g_y[(size_t)NROWS*DD];    // 128 MB
__device__ __half g_tokh[(size_t)NT*DD];    //  32 MB
__device__ __half g_w1h[(size_t)EE*FF*DD];  //  64 MB
__device__ __half g_w2h[(size_t)EE*DD*FF];  //  64 MB

// ---------------- helpers ----------------
__device__ __forceinline__ uint32_t s2u(const void* p) {
    uint32_t a;
    asm("{ .reg .u64 t; cvta.to.shared.u64 t, %1; cvt.u32.u64 %0, t; }" : "=r"(a) : "l"(p));
    return a;
}
__device__ __forceinline__ void cp16(uint32_t s, const void* g) {
    asm volatile("cp.async.cg.shared.global [%0], [%1], 16;" :: "r"(s), "l"(g));
}
__device__ __forceinline__ void cp_commit() {
    asm volatile("cp.async.commit_group;" ::: "memory");
}
template<int N>
__device__ __forceinline__ void cp_wait() {
    asm volatile("cp.async.wait_group %0;" :: "n"(N) : "memory");
}

// ---------------- prep: ALL fp32 -> fp16 conversions in one launch ----------------
__global__ void f2h_all_k(const float* __restrict__ tokens,
                          const float* __restrict__ w1,
                          const float* __restrict__ w2) {
    const long long n_tok = (long long)NT * DD / 4;
    const long long n_w1  = (long long)EE * FF * DD / 4;
    const long long n_w2  = (long long)EE * DD * FF / 4;
    long long i = (long long)blockIdx.x * blockDim.x + threadIdx.x;
    if (i >= n_tok + n_w1 + n_w2) return;
    const float* in; __half* out; long long j;
    if (i < n_tok)            { in = tokens; out = g_tokh; j = i; }
    else if (i < n_tok + n_w1){ in = w1;     out = g_w1h;  j = i - n_tok; }
    else                      { in = w2;     out = g_w2h;  j = i - n_tok - n_w1; }
    float4 v = reinterpret_cast<const float4*>(in)[j];
    __half2 h01 = __floats2half2_rn(v.x, v.y);
    __half2 h23 = __floats2half2_rn(v.z, v.w);
    uint2 pk;
    pk.x = *reinterpret_cast<uint32_t*>(&h01);
    pk.y = *reinterpret_cast<uint32_t*>(&h23);
    reinterpret_cast<uint2*>(out)[j] = pk;
}

// ---------------- routing ----------------
__global__ void gate_topk_k(const float* __restrict__ tokens,
                            const float* __restrict__ gw,
                            const float* __restrict__ gb) {
    int warp = threadIdx.x >> 5, lane = threadIdx.x & 31;
    int t = blockIdx.x * 8 + warp;
    const float* x = tokens + (size_t)t * DD;
    float xr[32];
#pragma unroll
    for (int c = 0; c < 32; c++) xr[c] = x[c * 32 + lane];
    float best0 = -1e30f, best1 = -1e30f;
    int e0 = 0, e1 = 0;
#pragma unroll
    for (int e = 0; e < EE; e++) {
        const float* w = gw + e * DD;
        float acc = 0.f;
#pragma unroll
        for (int c = 0; c < 32; c++) acc += xr[c] * w[c * 32 + lane];
#pragma unroll
        for (int o = 16; o > 0; o >>= 1) acc += __shfl_xor_sync(0xffffffffu, acc, o);
        acc += gb[e];
        if (acc > best0) { best1 = best0; e1 = e0; best0 = acc; e0 = e; }
        else if (acc > best1) { best1 = acc; e1 = e; }
    }
    if (lane == 0) {
        g_tope[t * 2] = (unsigned char)e0;
        g_tope[t * 2 + 1] = (unsigned char)e1;
        g_topv[t * 2] = best0;
        g_topv[t * 2 + 1] = best1;
        atomicAdd(&g_cnt[e0], 1);
        atomicAdd(&g_cnt[e1], 1);
    }
}

// single block: scan g_cnt, build compact (expert, m-block) work list, compact fill
__global__ void scan_fill_k() {
    __shared__ int sfill[EE];
    int tid = threadIdx.x;
    if (tid == 0) {
        int o = 0, w = 0;
        for (int e = 0; e < EE; e++) {
            g_off[e] = o;
            int c = g_cnt[e];
            o += c;
            for (int mb = 0; mb * BM < c; mb++) g_wrk[w++] = (e << 20) | mb;
        }
        g_off[EE] = o;
        g_nwrk = w;
    }
    if (tid < EE) sfill[tid] = 0;
    __syncthreads();
    for (int idx = tid; idx < NROWS; idx += blockDim.x) {
        int e = g_tope[idx];
        int pos = g_off[e] + atomicAdd(&sfill[e], 1);
        g_list[pos] = idx >> 1;
        g_slot[idx] = pos;
    }
}

__global__ void denom_k() {
    int b = blockIdx.x >> 1, k = blockIdx.x & 1;
    __shared__ float s[256];
    float a = 0.f;
    for (int i = 0; i < TT; i += 256) {
        int t = i + threadIdx.x;
        a += expf(g_topv[(size_t)(b * TT + t) * 2 + k]);
    }
    s[threadIdx.x] = a;
    __syncthreads();
    for (int o = 128; o > 0; o >>= 1) {
        if (threadIdx.x < o) s[threadIdx.x] += s[threadIdx.x + o];
        __syncthreads();
    }
    if (threadIdx.x == 0) g_denom[blockIdx.x] = s[0];
}

// ---------------- grouped GEMM (champion core + compact work list) ----------------
template<bool GATHER>
__global__ void __launch_bounds__(256) ffn_gemm(const float* __restrict__ bias,
                                                int Kdim, int Ntot) {
    int w = blockIdx.y;
    if (w >= g_nwrk) return;
    int e = g_wrk[w] >> 20;
    int mbase = (g_wrk[w] & 0xFFFFF) * BM;
    int cnt_e = g_cnt[e];
    int rowbase = g_off[e] + mbase;
    int nbase = blockIdx.x * BN;

    extern __shared__ __half smem[];
    uint32_t smem_u = s2u(smem);
    __shared__ const __half* arow[BM];

    int tid = threadIdx.x;
    if (tid < BM) {
        int r = (mbase + tid < cnt_e) ? tid : 0;
        int gr = rowbase + r;
        arow[tid] = GATHER ? (g_tokh + (size_t)g_list[gr] * Kdim)
                           : (g_h + (size_t)gr * Kdim);
    }
    __syncthreads();

    const __half* Bsrc = GATHER ? g_w1h : g_w2h;
    const __half* Bb = Bsrc + (size_t)e * Ntot * Kdim + (size_t)nbase * Kdim;

    wmma::fragment<wmma::accumulator, 16, 16, 16, float> acc[2][4];
#pragma unroll
    for (int i = 0; i < 2; i++)
#pragma unroll
        for (int j = 0; j < 4; j++) wmma::fill_fragment(acc[i][j], 0.f);

    int wid = tid >> 5;
    int wm = wid & 3;
    int wn = wid >> 2;

    int ktiles = Kdim / BKT;

    auto issue = [&](int s, int k0) {
        uint32_t base = smem_u + (uint32_t)s * TILE_BYTES;
#pragma unroll
        for (int i = 0; i < 4; i++) {
            int f = tid + i * 256;
            int r = f >> 3, c = (f & 7) * 8;
            uint32_t so = (uint32_t)(r * BKP + c) * 2;
            cp16(base + so, arow[r] + k0 + c);
            cp16(base + (uint32_t)BM * BKP * 2 + so, Bb + (size_t)r * Kdim + k0 + c);
        }
        cp_commit();
    };

    issue(0, 0);
    issue(1, BKT);

    for (int kt = 0; kt < ktiles; kt++) {
        cp_wait<NSTAGE - 2>();
        __syncthreads();
        if (kt + 2 < ktiles) issue((kt + 2) % NSTAGE, (kt + 2) * BKT);
        else                 cp_commit();

        const __half* As = smem + (size_t)((kt % NSTAGE)) * (2 * BM * BKP);
        const __half* Bs = As + BM * BKP;

#pragma unroll
        for (int kk = 0; kk < BKT; kk += 16) {
            wmma::fragment<wmma::matrix_a, 16, 16, 16, __half, wmma::row_major> af[2];
#pragma unroll
            for (int i = 0; i < 2; i++)
                wmma::load_matrix_sync(af[i], &As[(wm * 32 + i * 16) * BKP + kk], BKP);
#pragma unroll
            for (int j = 0; j < 4; j++) {
                wmma::fragment<wmma::matrix_b, 16, 16, 16, __half, wmma::col_major> bf;
                wmma::load_matrix_sync(bf, &Bs[(wn * 64 + j * 16) * BKP + kk], BKP);
#pragma unroll
                for (int i = 0; i < 2; i++)
                    wmma::mma_sync(acc[i][j], af[i], bf, acc[i][j]);
            }
        }
    }
    __syncthreads();

    // single-pass epilogue
    float* Cs = reinterpret_cast<float*>(smem);
#pragma unroll
    for (int i = 0; i < 2; i++)
#pragma unroll
        for (int j = 0; j < 4; j++)
            wmma::store_matrix_sync(&Cs[(wm * 32 + i * 16) * CN + wn * 64 + j * 16],
                                    acc[i][j], CN, wmma::mem_row_major);
    __syncthreads();

#pragma unroll
    for (int it = 0; it < 16; it++) {
        int f = tid + it * 256;
        int r = f >> 5, c = (f & 31) * 4;
        if (mbase + r < cnt_e) {
            float4 v = *reinterpret_cast<float4*>(&Cs[r * CN + c]);
            int col = nbase + c;
            float4 bb = *reinterpret_cast<const float4*>(bias + (size_t)e * Ntot + col);
            v.x += bb.x; v.y += bb.y; v.z += bb.z; v.w += bb.w;
            if (GATHER) {
                v.x = fmaxf(v.x, 0.f); v.y = fmaxf(v.y, 0.f);
                v.z = fmaxf(v.z, 0.f); v.w = fmaxf(v.w, 0.f);
                __half2 h01 = __floats2half2_rn(v.x, v.y);
                __half2 h23 = __floats2half2_rn(v.z, v.w);
                uint2 pk;
                pk.x = *reinterpret_cast<uint32_t*>(&h01);
                pk.y = *reinterpret_cast<uint32_t*>(&h23);
                *reinterpret_cast<uint2*>(&g_h[(size_t)(rowbase + r) * Ntot + col]) = pk;
            } else {
                *reinterpret_cast<float4*>(&g_y[(size_t)(rowbase + r) * Ntot + col]) = v;
            }
        }
    }
}

// out[t] = g0*y[slot0] + g1*y[slot1]; block 0 also resets g_cnt for next run
__global__ void combine_k(float* __restrict__ out) {
    int t = blockIdx.x;
    if (t == 0 && threadIdx.x < EE) g_cnt[threadIdx.x] = 0;
    int b = t / TT;
    float g0 = expf(g_topv[2 * t])     / g_denom[b * 2 + 0];
    float g1 = expf(g_topv[2 * t + 1]) / g_denom[b * 2 + 1];
    const float4* y0 = reinterpret_cast<const float4*>(g_y + (size_t)g_slot[2 * t] * DD);
    const float4* y1 = reinterpret_cast<const float4*>(g_y + (size_t)g_slot[2 * t + 1] * DD);
    float4 a = y0[threadIdx.x];
    float4 c = y1[threadIdx.x];
    float4 r;
    r.x = g0 * a.x + g1 * c.x;
    r.y = g0 * a.y + g1 * c.y;
    r.z = g0 * a.z + g1 * c.z;
    r.w = g0 * a.w + g1 * c.w;
    reinterpret_cast<float4*>(out + (size_t)t * DD)[threadIdx.x] = r;
}

// ---------------- launch: GEMM1 is launch index 3 (the profiled slot) ----------------
extern "C" void kernel_launch(void* const* d_in, const int* in_sizes, int n_in,
                              void* d_out, int out_size) {
    const float* tokens = (const float*)d_in[0];
    const float* gate_w = (const float*)d_in[1];
    const float* gate_b = (const float*)d_in[2];
    const float* w1     = (const float*)d_in[3];
    const float* b1     = (const float*)d_in[4];
    const float* w2     = (const float*)d_in[5];
    const float* b2     = (const float*)d_in[6];
    float* out = (float*)d_out;

    cudaFuncSetAttribute(ffn_gemm<true>,
                         cudaFuncAttributeMaxDynamicSharedMemorySize, SMEM_BYTES);
    cudaFuncSetAttribute(ffn_gemm<false>,
                         cudaFuncAttributeMaxDynamicSharedMemorySize, SMEM_BYTES);

    long long n4_total = (long long)NT * DD / 4 + (long long)EE * FF * DD / 2;
    f2h_all_k<<<(unsigned)((n4_total + 255) / 256), 256>>>(tokens, w1, w2);   // 0
    gate_topk_k<<<NT / 8, 256>>>(tokens, gate_w, gate_b);                      // 1
    scan_fill_k<<<1, 1024>>>();                                                // 2
    // compact grids: y = worst-case work items (264), real count read on device
    ffn_gemm<true><<<dim3(FF / BN, MAXWRK), 256, SMEM_BYTES>>>(b1, DD, FF);    // 3 <- ncu
    ffn_gemm<false><<<dim3(DD / BN, MAXWRK), 256, SMEM_BYTES>>>(b2, FF, DD);   // 4
    denom_k<<<BB * KK, 256>>>();                                               // 5
    combine_k<<<NT, 256>>>(out);                                               // 6
}

// round 15
// speedup vs baseline: 1.1419x; 1.0045x over previous
#include <cuda_runtime.h>
#include <cuda_fp16.h>
#include <mma.h>
#include <math.h>
#include <stdint.h>

using namespace nvcuda;

// Problem constants
#define BB 8
#define TT 2048
#define DD 1024
#define EE 8
#define FF 4096
#define KK 2
#define NT (BB*TT)          // 16384 tokens
#define NROWS (NT*KK)       // 32768 token-expert assignments

// GEMM tiling (champion config)
#define BM 128
#define BN 128
#define BKT 64
#define BKP 72
#define CN 132
#define TILE_BYTES (2*BM*BKP*2)        // 36864 B
#define NSTAGE 3
#define SMEM_BYTES (NSTAGE*TILE_BYTES) // 110592 B -> 2 CTAs/SM
#define MAXWRK (NROWS/BM + EE)         // 264 worst-case work items

// ---------------- device scratch (NEVER passed as kernel args from host) ----------------
__device__ int    g_cnt[EE];            // zero at load; reset by combine_k each run
__device__ int    g_off[EE+1];
__device__ int    g_nwrk;
__device__ int    g_wrk[MAXWRK];        // (e << 20) | m-block
__device__ int    g_list[NROWS];
__device__ int    g_slot[NROWS];
__device__ unsigned char g_tope[NROWS];
__device__ float  g_topv[NROWS];
__device__ float  g_denom[BB*KK];
__device__ __half g_h[(size_t)NROWS*FF];    // 256 MB
__device__ float  g_y[(size_t)NROWS*DD];    // 128 MB
__device__ __half g_tokh[(size_t)NT*DD];    //  32 MB
__device__ __half g_w1h[(size_t)EE*FF*DD];  //  64 MB
__device__ __half g_w2h[(size_t)EE*DD*FF];  //  64 MB

// ---------------- helpers ----------------
__device__ __forceinline__ uint32_t s2u(const void* p) {
    uint32_t a;
    asm("{ .reg .u64 t; cvta.to.shared.u64 t, %1; cvt.u32.u64 %0, t; }" : "=r"(a) : "l"(p));
    return a;
}
__device__ __forceinline__ void cp16(uint32_t s, const void* g) {
    asm volatile("cp.async.cg.shared.global [%0], [%1], 16;" :: "r"(s), "l"(g));
}
__device__ __forceinline__ void cp_commit() {
    asm volatile("cp.async.commit_group;" ::: "memory");
}
template<int N>
__device__ __forceinline__ void cp_wait() {
    asm volatile("cp.async.wait_group %0;" :: "n"(N) : "memory");
}
__device__ __forceinline__ void f2h_store(__half* out, const float* in, long long j) {
    float4 v = reinterpret_cast<const float4*>(in)[j];
    __half2 h01 = __floats2half2_rn(v.x, v.y);
    __half2 h23 = __floats2half2_rn(v.z, v.w);
    uint2 pk;
    pk.x = *reinterpret_cast<uint32_t*>(&h01);
    pk.y = *reinterpret_cast<uint32_t*>(&h23);
    reinterpret_cast<uint2*>(out)[j] = pk;
}

// ---------------- prep: tokens + w1 (needed by GEMM1) ----------------
__global__ void f2h_tokw1_k(const float* __restrict__ tokens,
                            const float* __restrict__ w1) {
    const long long n_tok = (long long)NT * DD / 4;
    const long long n_w1  = (long long)EE * FF * DD / 4;
    long long i = (long long)blockIdx.x * blockDim.x + threadIdx.x;
    if (i >= n_tok + n_w1) return;
    if (i < n_tok) f2h_store(g_tokh, tokens, i);
    else           f2h_store(g_w1h, w1, i - n_tok);
}

// ---------------- prep: w2 (needed only by GEMM2; overlapped with GEMM1) ----------------
__global__ void f2h_w2_k(const float* __restrict__ w2) {
    const long long n_w2 = (long long)EE * DD * FF / 4;
    long long i = (long long)blockIdx.x * blockDim.x + threadIdx.x;
    if (i >= n_w2) return;
    f2h_store(g_w2h, w2, i);
}

// ---------------- routing ----------------
__global__ void gate_topk_k(const float* __restrict__ tokens,
                            const float* __restrict__ gw,
                            const float* __restrict__ gb) {
    int warp = threadIdx.x >> 5, lane = threadIdx.x & 31;
    int t = blockIdx.x * 8 + warp;
    const float* x = tokens + (size_t)t * DD;
    float xr[32];
#pragma unroll
    for (int c = 0; c < 32; c++) xr[c] = x[c * 32 + lane];
    float best0 = -1e30f, best1 = -1e30f;
    int e0 = 0, e1 = 0;
#pragma unroll
    for (int e = 0; e < EE; e++) {
        const float* w = gw + e * DD;
        float acc = 0.f;
#pragma unroll
        for (int c = 0; c < 32; c++) acc += xr[c] * w[c * 32 + lane];
#pragma unroll
        for (int o = 16; o > 0; o >>= 1) acc += __shfl_xor_sync(0xffffffffu, acc, o);
        acc += gb[e];
        if (acc > best0) { best1 = best0; e1 = e0; best0 = acc; e0 = e; }
        else if (acc > best1) { best1 = acc; e1 = e; }
    }
    if (lane == 0) {
        g_tope[t * 2] = (unsigned char)e0;
        g_tope[t * 2 + 1] = (unsigned char)e1;
        g_topv[t * 2] = best0;
        g_topv[t * 2 + 1] = best1;
        atomicAdd(&g_cnt[e0], 1);
        atomicAdd(&g_cnt[e1], 1);
    }
}

// single block: scan g_cnt, build compact work list, compact fill
__global__ void scan_fill_k() {
    __shared__ int sfill[EE];
    int tid = threadIdx.x;
    if (tid == 0) {
        int o = 0, w = 0;
        for (int e = 0; e < EE; e++) {
            g_off[e] = o;
            int c = g_cnt[e];
            o += c;
            for (int mb = 0; mb * BM < c; mb++) g_wrk[w++] = (e << 20) | mb;
        }
        g_off[EE] = o;
        g_nwrk = w;
    }
    if (tid < EE) sfill[tid] = 0;
    __syncthreads();
    for (int idx = tid; idx < NROWS; idx += blockDim.x) {
        int e = g_tope[idx];
        int pos = g_off[e] + atomicAdd(&sfill[e], 1);
        g_list[pos] = idx >> 1;
        g_slot[idx] = pos;
    }
}

__global__ void denom_k() {
    int b = blockIdx.x >> 1, k = blockIdx.x & 1;
    __shared__ float s[256];
    float a = 0.f;
    for (int i = 0; i < TT; i += 256) {
        int t = i + threadIdx.x;
        a += expf(g_topv[(size_t)(b * TT + t) * 2 + k]);
    }
    s[threadIdx.x] = a;
    __syncthreads();
    for (int o = 128; o > 0; o >>= 1) {
        if (threadIdx.x < o) s[threadIdx.x] += s[threadIdx.x + o];
        __syncthreads();
    }
    if (threadIdx.x == 0) g_denom[blockIdx.x] = s[0];
}

// ---------------- grouped GEMM (unchanged champion core + compact work list) ----------------
template<bool GATHER>
__global__ void __launch_bounds__(256) ffn_gemm(const float* __restrict__ bias,
                                                int Kdim, int Ntot) {
    int w = blockIdx.y;
    if (w >= g_nwrk) return;
    int e = g_wrk[w] >> 20;
    int mbase = (g_wrk[w] & 0xFFFFF) * BM;
    int cnt_e = g_cnt[e];
    int rowbase = g_off[e] + mbase;
    int nbase = blockIdx.x * BN;

    extern __shared__ __half smem[];
    uint32_t smem_u = s2u(smem);
    __shared__ const __half* arow[BM];

    int tid = threadIdx.x;
    if (tid < BM) {
        int r = (mbase + tid < cnt_e) ? tid : 0;
        int gr = rowbase + r;
        arow[tid] = GATHER ? (g_tokh + (size_t)g_list[gr] * Kdim)
                           : (g_h + (size_t)gr * Kdim);
    }
    __syncthreads();

    const __half* Bsrc = GATHER ? g_w1h : g_w2h;
    const __half* Bb = Bsrc + (size_t)e * Ntot * Kdim + (size_t)nbase * Kdim;

    wmma::fragment<wmma::accumulator, 16, 16, 16, float> acc[2][4];
#pragma unroll
    for (int i = 0; i < 2; i++)
#pragma unroll
        for (int j = 0; j < 4; j++) wmma::fill_fragment(acc[i][j], 0.f);

    int wid = tid >> 5;
    int wm = wid & 3;
    int wn = wid >> 2;

    int ktiles = Kdim / BKT;

    auto issue = [&](int s, int k0) {
        uint32_t base = smem_u + (uint32_t)s * TILE_BYTES;
#pragma unroll
        for (int i = 0; i < 4; i++) {
            int f = tid + i * 256;
            int r = f >> 3, c = (f & 7) * 8;
            uint32_t so = (uint32_t)(r * BKP + c) * 2;
            cp16(base + so, arow[r] + k0 + c);
            cp16(base + (uint32_t)BM * BKP * 2 + so, Bb + (size_t)r * Kdim + k0 + c);
        }
        cp_commit();
    };

    issue(0, 0);
    issue(1, BKT);

    for (int kt = 0; kt < ktiles; kt++) {
        cp_wait<NSTAGE - 2>();
        __syncthreads();
        if (kt + 2 < ktiles) issue((kt + 2) % NSTAGE, (kt + 2) * BKT);
        else                 cp_commit();

        const __half* As = smem + (size_t)((kt % NSTAGE)) * (2 * BM * BKP);
        const __half* Bs = As + BM * BKP;

#pragma unroll
        for (int kk = 0; kk < BKT; kk += 16) {
            wmma::fragment<wmma::matrix_a, 16, 16, 16, __half, wmma::row_major> af[2];
#pragma unroll
            for (int i = 0; i < 2; i++)
                wmma::load_matrix_sync(af[i], &As[(wm * 32 + i * 16) * BKP + kk], BKP);
#pragma unroll
            for (int j = 0; j < 4; j++) {
                wmma::fragment<wmma::matrix_b, 16, 16, 16, __half, wmma::col_major> bf;
                wmma::load_matrix_sync(bf, &Bs[(wn * 64 + j * 16) * BKP + kk], BKP);
#pragma unroll
                for (int i = 0; i < 2; i++)
                    wmma::mma_sync(acc[i][j], af[i], bf, acc[i][j]);
            }
        }
    }
    __syncthreads();

    // single-pass epilogue
    float* Cs = reinterpret_cast<float*>(smem);
#pragma unroll
    for (int i = 0; i < 2; i++)
#pragma unroll
        for (int j = 0; j < 4; j++)
            wmma::store_matrix_sync(&Cs[(wm * 32 + i * 16) * CN + wn * 64 + j * 16],
                                    acc[i][j], CN, wmma::mem_row_major);
    __syncthreads();

#pragma unroll
    for (int it = 0; it < 16; it++) {
        int f = tid + it * 256;
        int r = f >> 5, c = (f & 31) * 4;
        if (mbase + r < cnt_e) {
            float4 v = *reinterpret_cast<float4*>(&Cs[r * CN + c]);
            int col = nbase + c;
            float4 bb = *reinterpret_cast<const float4*>(bias + (size_t)e * Ntot + col);
            v.x += bb.x; v.y += bb.y; v.z += bb.z; v.w += bb.w;
            if (GATHER) {
                v.x = fmaxf(v.x, 0.f); v.y = fmaxf(v.y, 0.f);
                v.z = fmaxf(v.z, 0.f); v.w = fmaxf(v.w, 0.f);
                __half2 h01 = __floats2half2_rn(v.x, v.y);
                __half2 h23 = __floats2half2_rn(v.z, v.w);
                uint2 pk;
                pk.x = *reinterpret_cast<uint32_t*>(&h01);
                pk.y = *reinterpret_cast<uint32_t*>(&h23);
                *reinterpret_cast<uint2*>(&g_h[(size_t)(rowbase + r) * Ntot + col]) = pk;
            } else {
                *reinterpret_cast<float4*>(&g_y[(size_t)(rowbase + r) * Ntot + col]) = v;
            }
        }
    }
}

// out[t] = g0*y[slot0] + g1*y[slot1]; block 0 also resets g_cnt for next run
__global__ void combine_k(float* __restrict__ out) {
    int t = blockIdx.x;
    if (t == 0 && threadIdx.x < EE) g_cnt[threadIdx.x] = 0;
    int b = t / TT;
    float g0 = expf(g_topv[2 * t])     / g_denom[b * 2 + 0];
    float g1 = expf(g_topv[2 * t + 1]) / g_denom[b * 2 + 1];
    const float4* y0 = reinterpret_cast<const float4*>(g_y + (size_t)g_slot[2 * t] * DD);
    const float4* y1 = reinterpret_cast<const float4*>(g_y + (size_t)g_slot[2 * t + 1] * DD);
    float4 a = y0[threadIdx.x];
    float4 c = y1[threadIdx.x];
    float4 r;
    r.x = g0 * a.x + g1 * c.x;
    r.y = g0 * a.y + g1 * c.y;
    r.z = g0 * a.z + g1 * c.z;
    r.w = g0 * a.w + g1 * c.w;
    reinterpret_cast<float4*>(out + (size_t)t * DD)[threadIdx.x] = r;
}

// ---------------- launch: capture-legal stream fork/join for overlap ----------------
extern "C" void kernel_launch(void* const* d_in, const int* in_sizes, int n_in,
                              void* d_out, int out_size) {
    const float* tokens = (const float*)d_in[0];
    const float* gate_w = (const float*)d_in[1];
    const float* gate_b = (const float*)d_in[2];
    const float* w1     = (const float*)d_in[3];
    const float* b1     = (const float*)d_in[4];
    const float* w2     = (const float*)d_in[5];
    const float* b2     = (const float*)d_in[6];
    float* out = (float*)d_out;

    static cudaStream_t sB = nullptr, sC = nullptr;
    static cudaEvent_t e0 = nullptr, eB = nullptr, eC = nullptr;
    static bool init_done = false;
    if (!init_done) {
        cudaStreamCreateWithFlags(&sB, cudaStreamNonBlocking);
        cudaStreamCreateWithFlags(&sC, cudaStreamNonBlocking);
        cudaEventCreateWithFlags(&e0, cudaEventDisableTiming);
        cudaEventCreateWithFlags(&eB, cudaEventDisableTiming);
        cudaEventCreateWithFlags(&eC, cudaEventDisableTiming);
        cudaFuncSetAttribute(ffn_gemm<true>,
                             cudaFuncAttributeMaxDynamicSharedMemorySize, SMEM_BYTES);
        cudaFuncSetAttribute(ffn_gemm<false>,
                             cudaFuncAttributeMaxDynamicSharedMemorySize, SMEM_BYTES);
        init_done = true;
    }

    // fork from the (legacy) capture stream
    cudaEventRecord(e0, 0);

    // side stream B: routing chain (depends only on fp32 tokens)
    cudaStreamWaitEvent(sB, e0, 0);
    gate_topk_k<<<NT / 8, 256, 0, sB>>>(tokens, gate_w, gate_b);
    scan_fill_k<<<1, 1024, 0, sB>>>();
    denom_k<<<BB * KK, 256, 0, sB>>>();
    cudaEventRecord(eB, sB);

    // side stream C: w2 conversion (needed only by GEMM2)
    cudaStreamWaitEvent(sC, e0, 0);
    {
        long long n4 = (long long)EE * DD * FF / 4;
        f2h_w2_k<<<(unsigned)((n4 + 255) / 256), 256, 0, sC>>>(w2);
    }
    cudaEventRecord(eC, sC);

    // main stream: tokens + w1 conversion, then GEMMs
    {
        long long n4 = (long long)NT * DD / 4 + (long long)EE * FF * DD / 4;
        f2h_tokw1_k<<<(unsigned)((n4 + 255) / 256), 256>>>(tokens, w1);
    }
    cudaStreamWaitEvent(0, eB, 0);   // routing ready
    ffn_gemm<true><<<dim3(FF / BN, MAXWRK), 256, SMEM_BYTES>>>(b1, DD, FF);
    cudaStreamWaitEvent(0, eC, 0);   // w2 ready
    ffn_gemm<false><<<dim3(DD / BN, MAXWRK), 256, SMEM_BYTES>>>(b2, FF, DD);
    combine_k<<<NT, 256>>>(out);
}

// round 17
// speedup vs baseline: 1.1433x; 1.0012x over previous
#include <cuda_runtime.h>
#include <cuda_fp16.h>
#include <mma.h>
#include <math.h>
#include <stdint.h>

using namespace nvcuda;

// Problem constants
#define BB 8
#define TT 2048
#define DD 1024
#define EE 8
#define FF 4096
#define KK 2
#define NT (BB*TT)          // 16384 tokens
#define NROWS (NT*KK)       // 32768 token-expert assignments

// GEMM tiling (champion config)
#define BM 128
#define BN 128
#define BKT 64
#define BKP 72
#define CN 132
#define TILE_BYTES (2*BM*BKP*2)        // 36864 B
#define NSTAGE 3
#define SMEM_BYTES (NSTAGE*TILE_BYTES) // 110592 B -> 2 CTAs/SM
#define MAXWRK (NROWS/BM + EE)         // 264 worst-case work items

// ---------------- device scratch (NEVER passed as kernel args from host) ----------------
__device__ int    g_cnt[EE];            // zero at load; reset by combine_k each run
__device__ int    g_off[EE+1];
__device__ int    g_nwrk;
__device__ int    g_wrk[MAXWRK];        // (e << 20) | m-block
__device__ int    g_list[NROWS];
__device__ int    g_slot[NROWS];
__device__ unsigned char g_tope[NROWS];
__device__ float  g_topv[NROWS];
__device__ float  g_denom[BB*KK];
__device__ __half g_h[(size_t)NROWS*FF];    // 256 MB
__device__ float  g_y[(size_t)NROWS*DD];    // 128 MB
__device__ __half g_tokh[(size_t)NT*DD];    //  32 MB
__device__ __half g_w1h[(size_t)EE*FF*DD];  //  64 MB
__device__ __half g_w2h[(size_t)EE*DD*FF];  //  64 MB

// ---------------- helpers ----------------
__device__ __forceinline__ uint32_t s2u(const void* p) {
    uint32_t a;
    asm("{ .reg .u64 t; cvta.to.shared.u64 t, %1; cvt.u32.u64 %0, t; }" : "=r"(a) : "l"(p));
    return a;
}
__device__ __forceinline__ void cp16(uint32_t s, const void* g) {
    asm volatile("cp.async.cg.shared.global [%0], [%1], 16;" :: "r"(s), "l"(g));
}
__device__ __forceinline__ void cp_commit() {
    asm volatile("cp.async.commit_group;" ::: "memory");
}
template<int N>
__device__ __forceinline__ void cp_wait() {
    asm volatile("cp.async.wait_group %0;" :: "n"(N) : "memory");
}
__device__ __forceinline__ void f2h_store(__half* out, const float* in, long long j) {
    float4 v = reinterpret_cast<const float4*>(in)[j];
    __half2 h01 = __floats2half2_rn(v.x, v.y);
    __half2 h23 = __floats2half2_rn(v.z, v.w);
    uint2 pk;
    pk.x = *reinterpret_cast<uint32_t*>(&h01);
    pk.y = *reinterpret_cast<uint32_t*>(&h23);
    reinterpret_cast<uint2*>(out)[j] = pk;
}

// ---------------- prep kernels ----------------
__global__ void f2h_tokw1_k(const float* __restrict__ tokens,
                            const float* __restrict__ w1) {
    const long long n_tok = (long long)NT * DD / 4;
    const long long n_w1  = (long long)EE * FF * DD / 4;
    long long i = (long long)blockIdx.x * blockDim.x + threadIdx.x;
    if (i >= n_tok + n_w1) return;
    if (i < n_tok) f2h_store(g_tokh, tokens, i);
    else           f2h_store(g_w1h, w1, i - n_tok);
}
__global__ void f2h_w2_k(const float* __restrict__ w2) {
    long long i = (long long)blockIdx.x * blockDim.x + threadIdx.x;
    if (i < (long long)EE * DD * FF / 4) f2h_store(g_w2h, w2, i);
}

// ---------------- routing ----------------
__global__ void gate_topk_k(const float* __restrict__ tokens,
                            const float* __restrict__ gw,
                            const float* __restrict__ gb) {
    int warp = threadIdx.x >> 5, lane = threadIdx.x & 31;
    int t = blockIdx.x * 8 + warp;
    const float* x = tokens + (size_t)t * DD;
    float xr[32];
#pragma unroll
    for (int c = 0; c < 32; c++) xr[c] = x[c * 32 + lane];
    float best0 = -1e30f, best1 = -1e30f;
    int e0 = 0, e1 = 0;
#pragma unroll
    for (int e = 0; e < EE; e++) {
        const float* w = gw + e * DD;
        float acc = 0.f;
#pragma unroll
        for (int c = 0; c < 32; c++) acc += xr[c] * w[c * 32 + lane];
#pragma unroll
        for (int o = 16; o > 0; o >>= 1) acc += __shfl_xor_sync(0xffffffffu, acc, o);
        acc += gb[e];
        if (acc > best0) { best1 = best0; e1 = e0; best0 = acc; e0 = e; }
        else if (acc > best1) { best1 = acc; e1 = e; }
    }
    if (lane == 0) {
        g_tope[t * 2] = (unsigned char)e0;
        g_tope[t * 2 + 1] = (unsigned char)e1;
        g_topv[t * 2] = best0;
        g_topv[t * 2 + 1] = best1;
        atomicAdd(&g_cnt[e0], 1);
        atomicAdd(&g_cnt[e1], 1);
    }
}

__global__ void scan_fill_k() {
    __shared__ int sfill[EE];
    int tid = threadIdx.x;
    if (tid == 0) {
        int o = 0, w = 0;
        for (int e = 0; e < EE; e++) {
            g_off[e] = o;
            int c = g_cnt[e];
            o += c;
            for (int mb = 0; mb * BM < c; mb++) g_wrk[w++] = (e << 20) | mb;
        }
        g_off[EE] = o;
        g_nwrk = w;
    }
    if (tid < EE) sfill[tid] = 0;
    __syncthreads();
    for (int idx = tid; idx < NROWS; idx += blockDim.x) {
        int e = g_tope[idx];
        int pos = g_off[e] + atomicAdd(&sfill[e], 1);
        g_list[pos] = idx >> 1;
        g_slot[idx] = pos;
    }
}

__global__ void denom_k() {
    int b = blockIdx.x >> 1, k = blockIdx.x & 1;
    __shared__ float s[256];
    float a = 0.f;
    for (int i = 0; i < TT; i += 256) {
        int t = i + threadIdx.x;
        a += expf(g_topv[(size_t)(b * TT + t) * 2 + k]);
    }
    s[threadIdx.x] = a;
    __syncthreads();
    for (int o = 128; o > 0; o >>= 1) {
        if (threadIdx.x < o) s[threadIdx.x] += s[threadIdx.x + o];
        __syncthreads();
    }
    if (threadIdx.x == 0) g_denom[blockIdx.x] = s[0];
}

// ---------------- grouped GEMM (champion core + expert-range filter) ----------------
template<bool GATHER>
__global__ void __launch_bounds__(256) ffn_gemm(const float* __restrict__ bias,
                                                int Kdim, int Ntot,
                                                int elo, int ehi) {
    int w = blockIdx.y;
    if (w >= g_nwrk) return;
    int e = g_wrk[w] >> 20;
    if (e < elo || e >= ehi) return;
    int mbase = (g_wrk[w] & 0xFFFFF) * BM;
    int cnt_e = g_cnt[e];
    int rowbase = g_off[e] + mbase;
    int nbase = blockIdx.x * BN;

    extern __shared__ __half smem[];
    uint32_t smem_u = s2u(smem);
    __shared__ const __half* arow[BM];

    int tid = threadIdx.x;
    if (tid < BM) {
        int r = (mbase + tid < cnt_e) ? tid : 0;
        int gr = rowbase + r;
        arow[tid] = GATHER ? (g_tokh + (size_t)g_list[gr] * Kdim)
                           : (g_h + (size_t)gr * Kdim);
    }
    __syncthreads();

    const __half* Bsrc = GATHER ? g_w1h : g_w2h;
    const __half* Bb = Bsrc + (size_t)e * Ntot * Kdim + (size_t)nbase * Kdim;

    wmma::fragment<wmma::accumulator, 16, 16, 16, float> acc[2][4];
#pragma unroll
    for (int i = 0; i < 2; i++)
#pragma unroll
        for (int j = 0; j < 4; j++) wmma::fill_fragment(acc[i][j], 0.f);

    int wid = tid >> 5;
    int wm = wid & 3;
    int wn = wid >> 2;

    int ktiles = Kdim / BKT;

    auto issue = [&](int s, int k0) {
        uint32_t base = smem_u + (uint32_t)s * TILE_BYTES;
#pragma unroll
        for (int i = 0; i < 4; i++) {
            int f = tid + i * 256;
            int r = f >> 3, c = (f & 7) * 8;
            uint32_t so = (uint32_t)(r * BKP + c) * 2;
            cp16(base + so, arow[r] + k0 + c);
            cp16(base + (uint32_t)BM * BKP * 2 + so, Bb + (size_t)r * Kdim + k0 + c);
        }
        cp_commit();
    };

    issue(0, 0);
    issue(1, BKT);

    for (int kt = 0; kt < ktiles; kt++) {
        cp_wait<NSTAGE - 2>();
        __syncthreads();
        if (kt + 2 < ktiles) issue((kt + 2) % NSTAGE, (kt + 2) * BKT);
        else                 cp_commit();

        const __half* As = smem + (size_t)((kt % NSTAGE)) * (2 * BM * BKP);
        const __half* Bs = As + BM * BKP;

#pragma unroll
        for (int kk = 0; kk < BKT; kk += 16) {
            wmma::fragment<wmma::matrix_a, 16, 16, 16, __half, wmma::row_major> af[2];
#pragma unroll
            for (int i = 0; i < 2; i++)
                wmma::load_matrix_sync(af[i], &As[(wm * 32 + i * 16) * BKP + kk], BKP);
#pragma unroll
            for (int j = 0; j < 4; j++) {
                wmma::fragment<wmma::matrix_b, 16, 16, 16, __half, wmma::col_major> bf;
                wmma::load_matrix_sync(bf, &Bs[(wn * 64 + j * 16) * BKP + kk], BKP);
#pragma unroll
                for (int i = 0; i < 2; i++)
                    wmma::mma_sync(acc[i][j], af[i], bf, acc[i][j]);
            }
        }
    }
    __syncthreads();

    float* Cs = reinterpret_cast<float*>(smem);
#pragma unroll
    for (int i = 0; i < 2; i++)
#pragma unroll
        for (int j = 0; j < 4; j++)
            wmma::store_matrix_sync(&Cs[(wm * 32 + i * 16) * CN + wn * 64 + j * 16],
                                    acc[i][j], CN, wmma::mem_row_major);
    __syncthreads();

#pragma unroll
    for (int it = 0; it < 16; it++) {
        int f = tid + it * 256;
        int r = f >> 5, c = (f & 31) * 4;
        if (mbase + r < cnt_e) {
            float4 v = *reinterpret_cast<float4*>(&Cs[r * CN + c]);
            int col = nbase + c;
            float4 bb = *reinterpret_cast<const float4*>(bias + (size_t)e * Ntot + col);
            v.x += bb.x; v.y += bb.y; v.z += bb.z; v.w += bb.w;
            if (GATHER) {
                v.x = fmaxf(v.x, 0.f); v.y = fmaxf(v.y, 0.f);
                v.z = fmaxf(v.z, 0.f); v.w = fmaxf(v.w, 0.f);
                __half2 h01 = __floats2half2_rn(v.x, v.y);
                __half2 h23 = __floats2half2_rn(v.z, v.w);
                uint2 pk;
                pk.x = *reinterpret_cast<uint32_t*>(&h01);
                pk.y = *reinterpret_cast<uint32_t*>(&h23);
                *reinterpret_cast<uint2*>(&g_h[(size_t)(rowbase + r) * Ntot + col]) = pk;
            } else {
                *reinterpret_cast<float4*>(&g_y[(size_t)(rowbase + r) * Ntot + col]) = v;
            }
        }
    }
}

// out[t] = g0*y[slot0] + g1*y[slot1]; block 0 also resets g_cnt for next run
__global__ void combine_k(float* __restrict__ out) {
    int t = blockIdx.x;
    if (t == 0 && threadIdx.x < EE) g_cnt[threadIdx.x] = 0;
    int b = t / TT;
    float g0 = expf(g_topv[2 * t])     / g_denom[b * 2 + 0];
    float g1 = expf(g_topv[2 * t + 1]) / g_denom[b * 2 + 1];
    const float4* y0 = reinterpret_cast<const float4*>(g_y + (size_t)g_slot[2 * t] * DD);
    const float4* y1 = reinterpret_cast<const float4*>(g_y + (size_t)g_slot[2 * t + 1] * DD);
    float4 a = y0[threadIdx.x];
    float4 c = y1[threadIdx.x];
    float4 r;
    r.x = g0 * a.x + g1 * c.x;
    r.y = g0 * a.y + g1 * c.y;
    r.z = g0 * a.z + g1 * c.z;
    r.w = g0 * a.w + g1 * c.w;
    reinterpret_cast<float4*>(out + (size_t)t * DD)[threadIdx.x] = r;
}

// ---------------- launch: chain split within the PROVEN r15 resource footprint ----------------
// 2 side streams + 3 events, events reused by re-recording (capture-legal).
extern "C" void kernel_launch(void* const* d_in, const int* in_sizes, int n_in,
                              void* d_out, int out_size) {
    const float* tokens = (const float*)d_in[0];
    const float* gate_w = (const float*)d_in[1];
    const float* gate_b = (const float*)d_in[2];
    const float* w1     = (const float*)d_in[3];
    const float* b1     = (const float*)d_in[4];
    const float* w2     = (const float*)d_in[5];
    const float* b2     = (const float*)d_in[6];
    float* out = (float*)d_out;

    static cudaStream_t sB = nullptr, sC = nullptr;
    static cudaEvent_t ev1 = nullptr, ev2 = nullptr, ev3 = nullptr;
    static bool init_done = false;
    if (!init_done) {
        cudaStreamCreateWithFlags(&sB, cudaStreamNonBlocking);
        cudaStreamCreateWithFlags(&sC, cudaStreamNonBlocking);
        cudaEventCreateWithFlags(&ev1, cudaEventDisableTiming);
        cudaEventCreateWithFlags(&ev2, cudaEventDisableTiming);
        cudaEventCreateWithFlags(&ev3, cudaEventDisableTiming);
        cudaFuncSetAttribute(ffn_gemm<true>,
                             cudaFuncAttributeMaxDynamicSharedMemorySize, SMEM_BYTES);
        cudaFuncSetAttribute(ffn_gemm<false>,
                             cudaFuncAttributeMaxDynamicSharedMemorySize, SMEM_BYTES);
        init_done = true;
    }

    const unsigned gw2  = (unsigned)(((long long)EE * DD * FF / 4 + 255) / 256);
    const unsigned gtw1 = (unsigned)(((long long)NT * DD / 4 +
                                      (long long)EE * FF * DD / 4 + 255) / 256);

    // a. fork
    cudaEventRecord(ev1, 0);

    // b. stream B: routing chain; ev2 = routing done
    cudaStreamWaitEvent(sB, ev1, 0);
    gate_topk_k<<<NT / 8, 256, 0, sB>>>(tokens, gate_w, gate_b);
    scan_fill_k<<<1, 1024, 0, sB>>>();
    denom_k<<<BB * KK, 256, 0, sB>>>();
    cudaEventRecord(ev2, sB);

    // c. stream C: w2 conversion; ev3 = w2 done
    cudaStreamWaitEvent(sC, ev1, 0);
    f2h_w2_k<<<gw2, 256, 0, sC>>>(w2);
    cudaEventRecord(ev3, sC);

    // d. main: tokens + w1 conversion; ev1 reused = prep done
    f2h_tokw1_k<<<gtw1, 256>>>(tokens, w1);
    cudaEventRecord(ev1, 0);

    // e/f. bind routing-done waits BEFORE ev2 is re-recorded
    cudaStreamWaitEvent(0, ev2, 0);    // main: routing ready
    cudaStreamWaitEvent(sC, ev2, 0);   // chain B: routing ready
    cudaStreamWaitEvent(sC, ev1, 0);   // chain B: prep ready

    // h. chain B (stream C): experts 4..7; ev2 reused = chain B done
    ffn_gemm<true><<<dim3(FF / BN, MAXWRK), 256, SMEM_BYTES, sC>>>(b1, DD, FF, EE / 2, EE);
    ffn_gemm<false><<<dim3(DD / BN, MAXWRK), 256, SMEM_BYTES, sC>>>(b2, FF, DD, EE / 2, EE);
    cudaEventRecord(ev2, sC);

    // i. chain A (main): experts 0..3
    ffn_gemm<true><<<dim3(FF / BN, MAXWRK), 256, SMEM_BYTES>>>(b1, DD, FF, 0, EE / 2);
    cudaStreamWaitEvent(0, ev3, 0);    // w2 ready
    ffn_gemm<false><<<dim3(DD / BN, MAXWRK), 256, SMEM_BYTES>>>(b2, FF, DD, 0, EE / 2);

    // j/k. join + combine
    cudaStreamWaitEvent(0, ev2, 0);    // chain B done
    combine_k<<<NT, 256>>>(out);
}